// round 13
// baseline (speedup 1.0000x reference)
#include <cuda_runtime.h>
#include <stdint.h>
#include <math.h>

#define NSEQ 256
#define TLEN 32
#define MROWS 8192      // NSEQ*TLEN
#define ENCD 200

// scratch (static device allocations are allowed)
__device__ float g_P  [MROWS * 800];
__device__ float g_Ya [MROWS * ENCD];
__device__ float g_Yb [MROWS * ENCD];
__device__ float g_enc[NSEQ * ENCD];
__device__ float g_stk[NSEQ * ENCD];

__device__ __forceinline__ float sigf(float x) { return 1.0f / (1.0f + expf(-x)); }
// accurate tanh via expf (robust even under fast-math)
__device__ __forceinline__ float tanh_acc(float x) {
    float e = expf(-2.0f * fabsf(x));
    float r = (1.0f - e) / (1.0f + e);
    return x >= 0.0f ? r : -r;
}
__device__ __forceinline__ float4 ldcg4(const float* p) {
    float4 v;
    asm volatile("ld.global.cg.v4.f32 {%0,%1,%2,%3}, [%4];"
                 : "=f"(v.x), "=f"(v.y), "=f"(v.z), "=f"(v.w) : "l"(p));
    return v;
}
__device__ __forceinline__ void stcg4(float* p, float4 v) {
    asm volatile("st.global.cg.v4.f32 [%0], {%1,%2,%3,%4};"
                 :: "l"(p), "f"(v.x), "f"(v.y), "f"(v.z), "f"(v.w));
}
__device__ __forceinline__ unsigned int smem_u32(const void* p) {
    unsigned int a;
    asm("{ .reg .u64 t; cvta.to.shared.u64 t, %1; cvt.u32.u64 %0, t; }"
        : "=r"(a) : "l"(p));
    return a;
}
__device__ __forceinline__ unsigned int ctarank() {
    unsigned int r; asm("mov.u32 %0, %%cluster_ctarank;" : "=r"(r)); return r;
}
__device__ __forceinline__ void st_remote_f32(unsigned int laddr, unsigned int rk, float v) {
    asm volatile(
        "{ .reg .b32 ra; mapa.shared::cluster.u32 ra, %0, %1; "
        "st.shared::cluster.f32 [ra], %2; }"
        :: "r"(laddr), "r"(rk), "f"(v) : "memory");
}
__device__ __forceinline__ void mbar_init(unsigned int addr, unsigned int count) {
    asm volatile("mbarrier.init.shared.b64 [%0], %1;" :: "r"(addr), "r"(count) : "memory");
}
// remote (or self) arrive, release.cluster semantics (default)
__device__ __forceinline__ void mbar_arrive_rank(unsigned int laddr, unsigned int rk) {
    asm volatile(
        "{ .reg .b32 ra; mapa.shared::cluster.u32 ra, %0, %1; "
        "mbarrier.arrive.shared::cluster.b64 _, [ra]; }"
        :: "r"(laddr), "r"(rk) : "memory");
}
// CTA-scope acquire wait (measured best)
__device__ __forceinline__ void mbar_wait_cta(unsigned int addr, unsigned int parity) {
    asm volatile(
        "{\n\t.reg .pred P1;\n\t"
        "WL%=:\n\t"
        "mbarrier.try_wait.parity.acquire.cta.shared::cta.b64 P1, [%0], %1, 0x989680;\n\t"
        "@P1 bra.uni WD%=;\n\t"
        "bra.uni WL%=;\n\t"
        "WD%=:\n\t}"
        :: "r"(addr), "r"(parity) : "memory");
}

// ---------------------------------------------------------------------------
// P[m][800] = A[row(m)][0:K] @ W[n][0:K]^T + bias[n]
// BM=128, BN=80, BK=20, 256 threads, 8x5 micro-tile
// ---------------------------------------------------------------------------
__global__ __launch_bounds__(256) void proj_gemm(
    const float* __restrict__ Asrc, const int* __restrict__ tok,
    const float* __restrict__ W, const float* __restrict__ bias,
    float* __restrict__ P, int K)
{
    __shared__ float As[20][132];   // k-major, 128 rows + 4 pad
    __shared__ float Ws[20][80];
    __shared__ long long roff[128];

    const int tid = threadIdx.x;
    const int M0 = blockIdx.x * 128;
    const int N0 = blockIdx.y * 80;

    if (tid < 128) {
        long long o = tok ? (long long)__ldg(&tok[M0 + tid]) * (long long)K
                          : (long long)(M0 + tid) * (long long)K;
        roff[tid] = o;
    }
    const int m0 = (tid >> 4) * 8;
    const int n0 = (tid & 15) * 5;

    float acc[8][5];
#pragma unroll
    for (int i = 0; i < 8; i++)
#pragma unroll
        for (int j = 0; j < 5; j++) acc[i][j] = 0.0f;
    __syncthreads();

    for (int kt = 0; kt < K; kt += 20) {
#pragma unroll
        for (int half = 0; half < 2; half++) {
            int i0 = (tid + half * 256) * 5;
            int mm = i0 / 20, kk = i0 % 20;
            const float* ap = Asrc + roff[mm] + kt + kk;
#pragma unroll
            for (int q = 0; q < 5; q++) As[kk + q][mm] = ap[q];
        }
        for (int i = tid; i < 1600; i += 256) {
            int nn = i / 20, kk = i % 20;
            Ws[kk][nn] = __ldg(&W[(size_t)(N0 + nn) * K + kt + kk]);
        }
        __syncthreads();
#pragma unroll
        for (int kk = 0; kk < 20; kk++) {
            float4 a4lo = *(const float4*)&As[kk][m0];
            float4 a4hi = *(const float4*)&As[kk][m0 + 4];
            float a[8] = {a4lo.x, a4lo.y, a4lo.z, a4lo.w,
                          a4hi.x, a4hi.y, a4hi.z, a4hi.w};
            float b[5];
#pragma unroll
            for (int j = 0; j < 5; j++) b[j] = Ws[kk][n0 + j];
#pragma unroll
            for (int i = 0; i < 8; i++)
#pragma unroll
                for (int j = 0; j < 5; j++) acc[i][j] += a[i] * b[j];
        }
        __syncthreads();
    }
#pragma unroll
    for (int i = 0; i < 8; i++) {
        size_t row = (size_t)(M0 + m0 + i) * 800 + N0 + n0;
#pragma unroll
        for (int j = 0; j < 5; j++)
            P[row + j] = acc[i][j] + __ldg(&bias[N0 + n0 + j]);
    }
}

// ---------------------------------------------------------------------------
// LSTM recurrence (400 threads, pipelined P loads, single accumulators).
// If encOut != null, fuse mean-pool, skip Y.
// ---------------------------------------------------------------------------
__global__ __launch_bounds__(400, 1) void lstm_rec(
    const float* __restrict__ P, const float* __restrict__ Whh2,
    const int* __restrict__ lengths, float* __restrict__ Y,
    float* __restrict__ encOut)
{
    extern __shared__ float sm[];
    float* sW = sm;
    float* sH = sm + 40000;
    float* sC = sH + 400;
    float* sG = sC + 400;

    const int tid = threadIdx.x;
    const int dir = blockIdx.y;
    const int sq0 = blockIdx.x * 4;

    const float* Wd = Whh2 + dir * 40000;
    for (int i = tid; i < 40000; i += 400) sW[i] = Wd[i];
    for (int i = tid; i < 800; i += 400) sm[40000 + i] = 0.0f;

    const int sPW = tid / 100;
    const int jPW = tid % 100;
    const int myLen = __ldg(&lengths[sq0 + sPW]);
    __syncthreads();

    const float4* sW4 = (const float4*)(sW + tid * 100);
    const float4* sH4 = (const float4*)sH;

    float p0, p1, p2, p3;
    {
        int t = dir ? (TLEN - 1) : 0;
        size_t base = ((size_t)sq0 * TLEN + t) * 800 + dir * 400 + tid;
        p0 = __ldg(&P[base]);
        p1 = __ldg(&P[base + 1 * TLEN * 800]);
        p2 = __ldg(&P[base + 2 * TLEN * 800]);
        p3 = __ldg(&P[base + 3 * TLEN * 800]);
    }
    float hsum = 0.0f;

    for (int st = 0; st < TLEN; st++) {
        int t = dir ? (TLEN - 1 - st) : st;
        float acc0 = p0, acc1 = p1, acc2 = p2, acc3 = p3;
        if (st + 1 < TLEN) {
            int tn = dir ? (TLEN - 2 - st) : (st + 1);
            size_t base = ((size_t)sq0 * TLEN + tn) * 800 + dir * 400 + tid;
            p0 = __ldg(&P[base]);
            p1 = __ldg(&P[base + 1 * TLEN * 800]);
            p2 = __ldg(&P[base + 2 * TLEN * 800]);
            p3 = __ldg(&P[base + 3 * TLEN * 800]);
        }
#pragma unroll
        for (int kq = 0; kq < 25; kq++) {
            float4 w = sW4[kq];
            float4 h0 = sH4[kq], h1 = sH4[25 + kq], h2 = sH4[50 + kq], h3 = sH4[75 + kq];
            acc0 += w.x * h0.x + w.y * h0.y + w.z * h0.z + w.w * h0.w;
            acc1 += w.x * h1.x + w.y * h1.y + w.z * h1.z + w.w * h1.w;
            acc2 += w.x * h2.x + w.y * h2.y + w.z * h2.z + w.w * h2.w;
            acc3 += w.x * h3.x + w.y * h3.y + w.z * h3.z + w.w * h3.w;
        }
        sG[tid] = acc0; sG[400 + tid] = acc1; sG[800 + tid] = acc2; sG[1200 + tid] = acc3;
        __syncthreads();
        {
            float gi = sG[sPW * 400 + jPW];
            float gf = sG[sPW * 400 + 100 + jPW];
            float gg = sG[sPW * 400 + 200 + jPW];
            float go = sG[sPW * 400 + 300 + jPW];
            float c  = sC[sPW * 100 + jPW];
            float cn = sigf(gf) * c + sigf(gi) * tanh_acc(gg);
            float hn = sigf(go) * tanh_acc(cn);
            float outv = 0.0f;
            if (t < myLen) {
                sC[sPW * 100 + jPW] = cn;
                sH[sPW * 100 + jPW] = hn;
                outv = hn;
            }
            if (encOut) hsum += outv;
            else Y[((size_t)(sq0 + sPW) * TLEN + t) * ENCD + dir * 100 + jPW] = outv;
        }
        __syncthreads();
    }
    if (encOut)
        encOut[(sq0 + sPW) * ENCD + dir * 100 + jPW] = hsum / (float)myLen;
}

// ---------------------------------------------------------------------------
// Parser: 8-CTA cluster, barrier only on reduce steps (round-11 structure).
// NEW: Wt stored warp-coalesced — slot ((w*25+q)*32+lane) float4 — so the
// speculative gate GEMV's LDS.128 is conflict-free (was degree-4 on the
// 800B row stride).
// ---------------------------------------------------------------------------
#define PRS_WT    0          // 16000 floats (5 warps x 25 q x 32 lanes x 4)
#define PRS_WA    16000      // 1200
#define PRS_BT    17200      // 72 (65 used)
#define PRS_BUF   17272      // 6 x 200
#define PRS_G     18472      // 72 (65 used)
#define PRS_MISS  18544      // 200
#define PRS_SC    18744      // 2
#define PRS_MBAR  18748      // 2 (8B aligned)
#define PRS_TOTAL 18752
#define PR_THREADS 224
#define PCLUSTER 8

__global__ __cluster_dims__(PCLUSTER, 1, 1) __launch_bounds__(PR_THREADS, 1) void parser8(
    const float* __restrict__ missing, const float* __restrict__ Wa,
    const float* __restrict__ ba, const float* __restrict__ Wt,
    const float* __restrict__ bt, float* __restrict__ out)
{
    extern __shared__ float sm[];
    float* sWt   = sm + PRS_WT;
    float* sWa   = sm + PRS_WA;
    float* sBt   = sm + PRS_BT;
    float* sBuf  = sm + PRS_BUF;
    float* sG    = sm + PRS_G;
    float* sMiss = sm + PRS_MISS;
    float* sSc   = sm + PRS_SC;
    const int tid = threadIdx.x;
    const unsigned int rank = ctarank();
    const int JC  = ((int)rank < 4) ? 13 : 12;          // units owned
    const int jlo = (int)rank * 12 + (((int)rank < 4) ? (int)rank : 4);
    const int NR  = 5 * JC;                              // gate rows owned
    const unsigned int mbarA = smem_u32(sm + PRS_MBAR);
    const unsigned int sBufA = smem_u32(sBuf);

    // Wt rows warp-coalesced: element (r, ph, q, e) -> worker thread wt=2r+ph,
    // slot float index = (((wt>>5)*25 + q)*32 + (wt&31))*4 + e
    for (int i = tid; i < NR * 200; i += PR_THREADS) {
        int r = i / 200, k = i - r * 200;
        int ph = k / 100, kk = k - ph * 100;
        int q = kk >> 2, e = kk & 3;
        int wt = 2 * r + ph;
        int slot = (((wt >> 5) * 25 + q) * 32 + (wt & 31)) * 4 + e;
        int grow = (r / JC) * 100 + jlo + (r % JC);
        sWt[slot] = __ldg(&Wt[grow * 200 + k]);
    }
    for (int i = tid; i < 1200; i += PR_THREADS) sWa[i] = __ldg(&Wa[i]);
    if (tid < NR) {
        int grow = (tid / JC) * 100 + jlo + (tid % JC);
        sBt[tid] = __ldg(&bt[grow]);
    }
    if (tid < 200) {
        float mv = __ldg(&missing[tid]);
        sMiss[tid] = mv;
        sBuf[0 * 200 + tid] = mv;                    // i1 = missing
        sBuf[1 * 200 + tid] = mv;                    // i0 = missing
        sBuf[2 * 200 + tid] = __ldg(&g_enc[tid]);    // ib = enc[0]
    }
    const float ba0 = __ldg(&ba[0]), ba1 = __ldg(&ba[1]);
    if (tid == 0) mbar_init(mbarA, PCLUSTER);
    __syncthreads();
    asm volatile("barrier.cluster.arrive.aligned;" ::: "memory");
    asm volatile("barrier.cluster.wait.aligned;"   ::: "memory");

    int i1 = 0, i0 = 1, ib = 2, ipre = 3, ibn = 4, isp = 5;
    int sp = 0, bp = 0;
    int rp = 0;                // reduce parity
    int pendWp = -1;           // pending merged -> g_stk writeback row
    const int warp = tid >> 5;

    for (int step = 0; step < 2 * NSEQ - 1; step++) {
        // ==== PHASE A: all independent work in parallel ====
        // warps 0-4: speculative gate GEMV, conflict-free warp-coalesced Wt
        if (tid < 2 * NR) {
            int ph = tid & 1;
            const float4* wp4 = (const float4*)sWt + ((tid >> 5) * 25) * 32 + (tid & 31);
            const float4* xp  = (const float4*)(sBuf + (ph ? i0 : i1) * 200);
            float acc = 0.0f;
#pragma unroll
            for (int q = 0; q < 25; q++) {
                float4 w = wp4[q * 32];
                float4 x = xp[q];
                acc += w.x * x.x + w.y * x.y + w.z * x.z + w.w * x.w;
            }
            unsigned msk = __activemask();
            acc += __shfl_xor_sync(msk, acc, 1);
            if (!ph) sG[tid >> 1] = acc + sBt[tid >> 1];
        }
        // warp 5: score GEMV (replicated in every CTA)
        if (warp == 5) {
            int lane = tid - 160;
            const float* w0 = sWa;
            const float* w1 = sWa + 600;
            const float* f1p = sBuf + i1 * 200;
            const float* f0p = sBuf + i0 * 200;
            const float* fbp = sBuf + ib * 200;
            float a0 = 0.0f, a1 = 0.0f;
#pragma unroll
            for (int k = 0; k < 7; k++) {
                int kk = lane + 32 * k;
                if (kk < 200) { float f = f1p[kk]; a0 += w0[kk] * f;       a1 += w1[kk] * f; }
            }
#pragma unroll
            for (int k = 0; k < 7; k++) {
                int kk = lane + 32 * k;
                if (kk < 200) { float f = f0p[kk]; a0 += w0[200 + kk] * f; a1 += w1[200 + kk] * f; }
            }
#pragma unroll
            for (int k = 0; k < 7; k++) {
                int kk = lane + 32 * k;
                if (kk < 200) { float f = fbp[kk]; a0 += w0[400 + kk] * f; a1 += w1[400 + kk] * f; }
            }
#pragma unroll
            for (int o = 16; o > 0; o >>= 1) {
                a0 += __shfl_down_sync(0xffffffffu, a0, o);
                a1 += __shfl_down_sync(0xffffffffu, a1, o);
            }
            if (lane == 0) { sSc[0] = a0 + ba0; sSc[1] = a1 + ba1; }
        }
        // warp 6: pending merged writeback + prefetch stack[sp-3], enc[bp+1]
        if (warp == 6) {
            int lane = tid - 192;
            if (pendWp >= 0) {
                const float4* src = (const float4*)(sBuf + i0 * 200);
                for (int q = lane; q < 50; q += 32)
                    stcg4(&g_stk[pendWp * ENCD + 4 * q], src[q]);
            }
            float4* dpre = (float4*)(sBuf + ipre * 200);
            float4* dbn  = (float4*)(sBuf + ibn  * 200);
            const float4* mi4 = (const float4*)sMiss;
            for (int q = lane; q < 50; q += 32)
                dpre[q] = (sp >= 3) ? ldcg4(&g_stk[(sp - 3) * ENCD + 4 * q]) : mi4[q];
            int nbp = bp + 1;
            for (int q = lane; q < 50; q += 32)
                dbn[q] = (nbp < NSEQ) ? __ldg(((const float4*)(g_enc + nbp * ENCD)) + q)
                                      : mi4[q];
        }
        pendWp = -1;
        __syncthreads();

        // ==== PHASE B ====
        float m0 = (bp < NSEQ) ? sSc[0] : -1e30f;
        float m1 = (sp >= 2)   ? sSc[1] : -1e30f;
        bool is_shift = (m0 >= m1);   // argmax, first-index tie-break

        if (is_shift) {
            // push FULL b vector (CTA-redundant stack) — no cluster sync
            if (warp == 0 && tid < 25) {
                const float4* src = (const float4*)(sBuf + ib * 200);
                stcg4(&g_stk[sp * ENCD + 8 * tid],     src[2 * tid]);
                stcg4(&g_stk[sp * ENCD + 8 * tid + 4], src[2 * tid + 1]);
            }
            int t = i1; i1 = i0; i0 = ib; ib = ibn; ibn = t;
            sp += 1; bp += 1;
        } else {
            if (warp == 0) {
                if (tid < JC) {
                    int u = tid;
                    int j = jlo + u;
                    float gi = sG[u],          gf1 = sG[JC + u], gf2 = sG[2 * JC + u];
                    float go = sG[3 * JC + u], gu  = sG[4 * JC + u];
                    float c1 = sBuf[i1 * 200 + 100 + j];
                    float c2 = sBuf[i0 * 200 + 100 + j];
                    float c = sigf(gf1) * c1 + sigf(gf2) * c2 + sigf(gi) * tanh_acc(gu);
                    float h = sigf(go) * tanh_acc(c);
                    sBuf[isp * 200 + j]       = h;
                    sBuf[isp * 200 + 100 + j] = c;
                    unsigned int ah = sBufA + (unsigned int)(isp * 200 + j) * 4u;
                    unsigned int ac = sBufA + (unsigned int)(isp * 200 + 100 + j) * 4u;
#pragma unroll
                    for (unsigned int rk = 0; rk < PCLUSTER; rk++) {
                        if (rk != rank) { st_remote_f32(ah, rk, h); st_remote_f32(ac, rk, c); }
                    }
                }
                __syncwarp(0xffffffffu);
                if (tid < PCLUSTER) mbar_arrive_rank(mbarA, (unsigned int)tid);
            }
            mbar_wait_cta(mbarA, (unsigned int)rp);
            rp ^= 1;
            pendWp = sp - 2;           // merged -> g_stk next step (off path)
            int n1 = ipre, n0 = isp;
            ipre = i1; isp = i0;
            i1 = n1; i0 = n0;          // merged now at i0
            sp -= 1;
        }
    }

    // final stack[0] = last merged = sBuf[i0] (h | c)
    if (rank == 0 && tid < 200) out[tid] = sBuf[i0 * 200 + tid];
}

// ---------------------------------------------------------------------------
extern "C" void kernel_launch(void* const* d_in, const int* in_sizes, int n_in,
                              void* d_out, int out_size)
{
    const int*   tokens  = (const int*)d_in[0];
    const int*   lengths = (const int*)d_in[1];
    const float* emb     = (const float*)d_in[2];
    const float* Wih0    = (const float*)d_in[3];
    const float* Whh0    = (const float*)d_in[4];
    const float* b0      = (const float*)d_in[5];
    const float* Wih12   = (const float*)d_in[6];
    const float* Whh12   = (const float*)d_in[7];
    const float* b12     = (const float*)d_in[8];
    const float* missing = (const float*)d_in[9];
    const float* Wa      = (const float*)d_in[10];
    const float* ba      = (const float*)d_in[11];
    const float* Wt      = (const float*)d_in[12];
    const float* bt      = (const float*)d_in[13];
    float* out = (float*)d_out;

    float *P, *Ya, *Yb, *enc;
    cudaGetSymbolAddress((void**)&P,  g_P);
    cudaGetSymbolAddress((void**)&Ya, g_Ya);
    cudaGetSymbolAddress((void**)&Yb, g_Yb);
    cudaGetSymbolAddress((void**)&enc, g_enc);

    const int lstmSmem = (40000 + 400 + 400 + 1600) * 4;   // 169600
    const int parsSmem = PRS_TOTAL * 4;                    // 75008
    cudaFuncSetAttribute(lstm_rec, cudaFuncAttributeMaxDynamicSharedMemorySize, lstmSmem);
    cudaFuncSetAttribute(parser8, cudaFuncAttributeMaxDynamicSharedMemorySize, parsSmem);

    dim3 gg(64, 10), rg(64, 2);

    // layer 0
    proj_gemm<<<gg, 256>>>(emb, tokens, Wih0, b0, P, 300);
    lstm_rec<<<rg, 400, lstmSmem>>>(P, Whh0, lengths, Ya, nullptr);
    // layer 1
    proj_gemm<<<gg, 256>>>(Ya, nullptr, Wih12, b12, P, 200);
    lstm_rec<<<rg, 400, lstmSmem>>>(P, Whh12, lengths, Yb, nullptr);
    // layer 2 (+ fused meanpool -> enc)
    proj_gemm<<<gg, 256>>>(Yb, nullptr, Wih12 + 160000, b12 + 800, P, 200);
    lstm_rec<<<rg, 400, lstmSmem>>>(P, Whh12 + 80000, lengths, nullptr, enc);
    // parse
    parser8<<<PCLUSTER, PR_THREADS, parsSmem>>>(missing, Wa, ba, Wt, bt, out);
}

// round 14
// speedup vs baseline: 1.0070x; 1.0070x over previous
#include <cuda_runtime.h>
#include <stdint.h>
#include <math.h>

#define NSEQ 256
#define TLEN 32
#define MROWS 8192      // NSEQ*TLEN
#define ENCD 200

// scratch (static device allocations are allowed)
__device__ float g_P  [MROWS * 800];
__device__ float g_Ya [MROWS * ENCD];
__device__ float g_Yb [MROWS * ENCD];
__device__ float g_enc[NSEQ * ENCD];
__device__ float g_stk[NSEQ * ENCD];

__device__ __forceinline__ float sigf(float x) { return 1.0f / (1.0f + expf(-x)); }
// accurate tanh via expf (robust even under fast-math)
__device__ __forceinline__ float tanh_acc(float x) {
    float e = expf(-2.0f * fabsf(x));
    float r = (1.0f - e) / (1.0f + e);
    return x >= 0.0f ? r : -r;
}
__device__ __forceinline__ float4 ldcg4(const float* p) {
    float4 v;
    asm volatile("ld.global.cg.v4.f32 {%0,%1,%2,%3}, [%4];"
                 : "=f"(v.x), "=f"(v.y), "=f"(v.z), "=f"(v.w) : "l"(p));
    return v;
}
__device__ __forceinline__ void stcg4(float* p, float4 v) {
    asm volatile("st.global.cg.v4.f32 [%0], {%1,%2,%3,%4};"
                 :: "l"(p), "f"(v.x), "f"(v.y), "f"(v.z), "f"(v.w));
}
__device__ __forceinline__ unsigned int smem_u32(const void* p) {
    unsigned int a;
    asm("{ .reg .u64 t; cvta.to.shared.u64 t, %1; cvt.u32.u64 %0, t; }"
        : "=r"(a) : "l"(p));
    return a;
}
__device__ __forceinline__ unsigned int ctarank() {
    unsigned int r; asm("mov.u32 %0, %%cluster_ctarank;" : "=r"(r)); return r;
}
__device__ __forceinline__ void st_remote_f32(unsigned int laddr, unsigned int rk, float v) {
    asm volatile(
        "{ .reg .b32 ra; mapa.shared::cluster.u32 ra, %0, %1; "
        "st.shared::cluster.f32 [ra], %2; }"
        :: "r"(laddr), "r"(rk), "f"(v) : "memory");
}
__device__ __forceinline__ void mbar_init(unsigned int addr, unsigned int count) {
    asm volatile("mbarrier.init.shared.b64 [%0], %1;" :: "r"(addr), "r"(count) : "memory");
}
// remote (or self) arrive, release.cluster semantics (default)
__device__ __forceinline__ void mbar_arrive_rank(unsigned int laddr, unsigned int rk) {
    asm volatile(
        "{ .reg .b32 ra; mapa.shared::cluster.u32 ra, %0, %1; "
        "mbarrier.arrive.shared::cluster.b64 _, [ra]; }"
        :: "r"(laddr), "r"(rk) : "memory");
}
// CTA-scope acquire wait (measured best)
__device__ __forceinline__ void mbar_wait_cta(unsigned int addr, unsigned int parity) {
    asm volatile(
        "{\n\t.reg .pred P1;\n\t"
        "WL%=:\n\t"
        "mbarrier.try_wait.parity.acquire.cta.shared::cta.b64 P1, [%0], %1, 0x989680;\n\t"
        "@P1 bra.uni WD%=;\n\t"
        "bra.uni WL%=;\n\t"
        "WD%=:\n\t}"
        :: "r"(addr), "r"(parity) : "memory");
}

// ---------------------------------------------------------------------------
// P[m][800] = A[row(m)][0:K] @ W[n][0:K]^T + bias[n]
// BM=128, BN=80, BK=20, 256 threads, 8x5 micro-tile
// ---------------------------------------------------------------------------
__global__ __launch_bounds__(256) void proj_gemm(
    const float* __restrict__ Asrc, const int* __restrict__ tok,
    const float* __restrict__ W, const float* __restrict__ bias,
    float* __restrict__ P, int K)
{
    __shared__ float As[20][132];   // k-major, 128 rows + 4 pad
    __shared__ float Ws[20][80];
    __shared__ long long roff[128];

    const int tid = threadIdx.x;
    const int M0 = blockIdx.x * 128;
    const int N0 = blockIdx.y * 80;

    if (tid < 128) {
        long long o = tok ? (long long)__ldg(&tok[M0 + tid]) * (long long)K
                          : (long long)(M0 + tid) * (long long)K;
        roff[tid] = o;
    }
    const int m0 = (tid >> 4) * 8;
    const int n0 = (tid & 15) * 5;

    float acc[8][5];
#pragma unroll
    for (int i = 0; i < 8; i++)
#pragma unroll
        for (int j = 0; j < 5; j++) acc[i][j] = 0.0f;
    __syncthreads();

    for (int kt = 0; kt < K; kt += 20) {
#pragma unroll
        for (int half = 0; half < 2; half++) {
            int i0 = (tid + half * 256) * 5;
            int mm = i0 / 20, kk = i0 % 20;
            const float* ap = Asrc + roff[mm] + kt + kk;
#pragma unroll
            for (int q = 0; q < 5; q++) As[kk + q][mm] = ap[q];
        }
        for (int i = tid; i < 1600; i += 256) {
            int nn = i / 20, kk = i % 20;
            Ws[kk][nn] = __ldg(&W[(size_t)(N0 + nn) * K + kt + kk]);
        }
        __syncthreads();
#pragma unroll
        for (int kk = 0; kk < 20; kk++) {
            float4 a4lo = *(const float4*)&As[kk][m0];
            float4 a4hi = *(const float4*)&As[kk][m0 + 4];
            float a[8] = {a4lo.x, a4lo.y, a4lo.z, a4lo.w,
                          a4hi.x, a4hi.y, a4hi.z, a4hi.w};
            float b[5];
#pragma unroll
            for (int j = 0; j < 5; j++) b[j] = Ws[kk][n0 + j];
#pragma unroll
            for (int i = 0; i < 8; i++)
#pragma unroll
                for (int j = 0; j < 5; j++) acc[i][j] += a[i] * b[j];
        }
        __syncthreads();
    }
#pragma unroll
    for (int i = 0; i < 8; i++) {
        size_t row = (size_t)(M0 + m0 + i) * 800 + N0 + n0;
#pragma unroll
        for (int j = 0; j < 5; j++)
            P[row + j] = acc[i][j] + __ldg(&bias[N0 + n0 + j]);
    }
}

// ---------------------------------------------------------------------------
// LSTM recurrence: Whh REGISTER-RESIDENT (25 float4/thread, loaded once).
// Inner loop reads only broadcast LDS for h — removes 160 KB/step of
// per-thread-distinct smem traffic. smem = 2400 floats only.
// If encOut != null, fuse mean-pool, skip Y.
// ---------------------------------------------------------------------------
__global__ __launch_bounds__(400, 1) void lstm_rec(
    const float* __restrict__ P, const float* __restrict__ Whh2,
    const int* __restrict__ lengths, float* __restrict__ Y,
    float* __restrict__ encOut)
{
    __shared__ float sH[400];
    __shared__ float sC[400];
    __shared__ float sG[1600];

    const int tid = threadIdx.x;
    const int dir = blockIdx.y;
    const int sq0 = blockIdx.x * 4;

    // Whh row -> registers (row base tid*400B is 16B-aligned)
    float4 w[25];
    {
        const float4* wg = (const float4*)(Whh2 + dir * 40000 + tid * 100);
#pragma unroll
        for (int q = 0; q < 25; q++) w[q] = __ldg(&wg[q]);
    }

    if (tid < 400) { sH[tid] = 0.0f; sC[tid] = 0.0f; }

    const int sPW = tid / 100;
    const int jPW = tid % 100;
    const int myLen = __ldg(&lengths[sq0 + sPW]);
    __syncthreads();

    const float4* sH4 = (const float4*)sH;

    float p0, p1, p2, p3;
    {
        int t = dir ? (TLEN - 1) : 0;
        size_t base = ((size_t)sq0 * TLEN + t) * 800 + dir * 400 + tid;
        p0 = __ldg(&P[base]);
        p1 = __ldg(&P[base + 1 * TLEN * 800]);
        p2 = __ldg(&P[base + 2 * TLEN * 800]);
        p3 = __ldg(&P[base + 3 * TLEN * 800]);
    }
    float hsum = 0.0f;

    for (int st = 0; st < TLEN; st++) {
        int t = dir ? (TLEN - 1 - st) : st;
        float acc0 = p0, acc1 = p1, acc2 = p2, acc3 = p3;
        if (st + 1 < TLEN) {
            int tn = dir ? (TLEN - 2 - st) : (st + 1);
            size_t base = ((size_t)sq0 * TLEN + tn) * 800 + dir * 400 + tid;
            p0 = __ldg(&P[base]);
            p1 = __ldg(&P[base + 1 * TLEN * 800]);
            p2 = __ldg(&P[base + 2 * TLEN * 800]);
            p3 = __ldg(&P[base + 3 * TLEN * 800]);
        }
#pragma unroll
        for (int kq = 0; kq < 25; kq++) {
            float4 wq = w[kq];
            float4 h0 = sH4[kq], h1 = sH4[25 + kq], h2 = sH4[50 + kq], h3 = sH4[75 + kq];
            acc0 += wq.x * h0.x + wq.y * h0.y + wq.z * h0.z + wq.w * h0.w;
            acc1 += wq.x * h1.x + wq.y * h1.y + wq.z * h1.z + wq.w * h1.w;
            acc2 += wq.x * h2.x + wq.y * h2.y + wq.z * h2.z + wq.w * h2.w;
            acc3 += wq.x * h3.x + wq.y * h3.y + wq.z * h3.z + wq.w * h3.w;
        }
        sG[tid] = acc0; sG[400 + tid] = acc1; sG[800 + tid] = acc2; sG[1200 + tid] = acc3;
        __syncthreads();
        {
            float gi = sG[sPW * 400 + jPW];
            float gf = sG[sPW * 400 + 100 + jPW];
            float gg = sG[sPW * 400 + 200 + jPW];
            float go = sG[sPW * 400 + 300 + jPW];
            float c  = sC[sPW * 100 + jPW];
            float cn = sigf(gf) * c + sigf(gi) * tanh_acc(gg);
            float hn = sigf(go) * tanh_acc(cn);
            float outv = 0.0f;
            if (t < myLen) {
                sC[sPW * 100 + jPW] = cn;
                sH[sPW * 100 + jPW] = hn;
                outv = hn;
            }
            if (encOut) hsum += outv;
            else Y[((size_t)(sq0 + sPW) * TLEN + t) * ENCD + dir * 100 + jPW] = outv;
        }
        __syncthreads();
    }
    if (encOut)
        encOut[(sq0 + sPW) * ENCD + dir * 100 + jPW] = hsum / (float)myLen;
}

// ---------------------------------------------------------------------------
// Parser: unchanged from the current passing version (8-CTA cluster,
// barrier only on reduce steps, warp-coalesced Wt, CTA-redundant stack).
// ---------------------------------------------------------------------------
#define PRS_WT    0          // 16000 floats (5 warps x 25 q x 32 lanes x 4)
#define PRS_WA    16000      // 1200
#define PRS_BT    17200      // 72 (65 used)
#define PRS_BUF   17272      // 6 x 200
#define PRS_G     18472      // 72 (65 used)
#define PRS_MISS  18544      // 200
#define PRS_SC    18744      // 2
#define PRS_MBAR  18748      // 2 (8B aligned)
#define PRS_TOTAL 18752
#define PR_THREADS 224
#define PCLUSTER 8

__global__ __cluster_dims__(PCLUSTER, 1, 1) __launch_bounds__(PR_THREADS, 1) void parser8(
    const float* __restrict__ missing, const float* __restrict__ Wa,
    const float* __restrict__ ba, const float* __restrict__ Wt,
    const float* __restrict__ bt, float* __restrict__ out)
{
    extern __shared__ float sm[];
    float* sWt   = sm + PRS_WT;
    float* sWa   = sm + PRS_WA;
    float* sBt   = sm + PRS_BT;
    float* sBuf  = sm + PRS_BUF;
    float* sG    = sm + PRS_G;
    float* sMiss = sm + PRS_MISS;
    float* sSc   = sm + PRS_SC;
    const int tid = threadIdx.x;
    const unsigned int rank = ctarank();
    const int JC  = ((int)rank < 4) ? 13 : 12;          // units owned
    const int jlo = (int)rank * 12 + (((int)rank < 4) ? (int)rank : 4);
    const int NR  = 5 * JC;                              // gate rows owned
    const unsigned int mbarA = smem_u32(sm + PRS_MBAR);
    const unsigned int sBufA = smem_u32(sBuf);

    // Wt rows warp-coalesced: element (r, ph, q, e) -> worker thread wt=2r+ph,
    // slot float index = (((wt>>5)*25 + q)*32 + (wt&31))*4 + e
    for (int i = tid; i < NR * 200; i += PR_THREADS) {
        int r = i / 200, k = i - r * 200;
        int ph = k / 100, kk = k - ph * 100;
        int q = kk >> 2, e = kk & 3;
        int wt = 2 * r + ph;
        int slot = (((wt >> 5) * 25 + q) * 32 + (wt & 31)) * 4 + e;
        int grow = (r / JC) * 100 + jlo + (r % JC);
        sWt[slot] = __ldg(&Wt[grow * 200 + k]);
    }
    for (int i = tid; i < 1200; i += PR_THREADS) sWa[i] = __ldg(&Wa[i]);
    if (tid < NR) {
        int grow = (tid / JC) * 100 + jlo + (tid % JC);
        sBt[tid] = __ldg(&bt[grow]);
    }
    if (tid < 200) {
        float mv = __ldg(&missing[tid]);
        sMiss[tid] = mv;
        sBuf[0 * 200 + tid] = mv;                    // i1 = missing
        sBuf[1 * 200 + tid] = mv;                    // i0 = missing
        sBuf[2 * 200 + tid] = __ldg(&g_enc[tid]);    // ib = enc[0]
    }
    const float ba0 = __ldg(&ba[0]), ba1 = __ldg(&ba[1]);
    if (tid == 0) mbar_init(mbarA, PCLUSTER);
    __syncthreads();
    asm volatile("barrier.cluster.arrive.aligned;" ::: "memory");
    asm volatile("barrier.cluster.wait.aligned;"   ::: "memory");

    int i1 = 0, i0 = 1, ib = 2, ipre = 3, ibn = 4, isp = 5;
    int sp = 0, bp = 0;
    int rp = 0;                // reduce parity
    int pendWp = -1;           // pending merged -> g_stk writeback row
    const int warp = tid >> 5;

    for (int step = 0; step < 2 * NSEQ - 1; step++) {
        // ==== PHASE A: all independent work in parallel ====
        // warps 0-4: speculative gate GEMV, conflict-free warp-coalesced Wt
        if (tid < 2 * NR) {
            int ph = tid & 1;
            const float4* wp4 = (const float4*)sWt + ((tid >> 5) * 25) * 32 + (tid & 31);
            const float4* xp  = (const float4*)(sBuf + (ph ? i0 : i1) * 200);
            float acc = 0.0f;
#pragma unroll
            for (int q = 0; q < 25; q++) {
                float4 w = wp4[q * 32];
                float4 x = xp[q];
                acc += w.x * x.x + w.y * x.y + w.z * x.z + w.w * x.w;
            }
            unsigned msk = __activemask();
            acc += __shfl_xor_sync(msk, acc, 1);
            if (!ph) sG[tid >> 1] = acc + sBt[tid >> 1];
        }
        // warp 5: score GEMV (replicated in every CTA)
        if (warp == 5) {
            int lane = tid - 160;
            const float* w0 = sWa;
            const float* w1 = sWa + 600;
            const float* f1p = sBuf + i1 * 200;
            const float* f0p = sBuf + i0 * 200;
            const float* fbp = sBuf + ib * 200;
            float a0 = 0.0f, a1 = 0.0f;
#pragma unroll
            for (int k = 0; k < 7; k++) {
                int kk = lane + 32 * k;
                if (kk < 200) { float f = f1p[kk]; a0 += w0[kk] * f;       a1 += w1[kk] * f; }
            }
#pragma unroll
            for (int k = 0; k < 7; k++) {
                int kk = lane + 32 * k;
                if (kk < 200) { float f = f0p[kk]; a0 += w0[200 + kk] * f; a1 += w1[200 + kk] * f; }
            }
#pragma unroll
            for (int k = 0; k < 7; k++) {
                int kk = lane + 32 * k;
                if (kk < 200) { float f = fbp[kk]; a0 += w0[400 + kk] * f; a1 += w1[400 + kk] * f; }
            }
#pragma unroll
            for (int o = 16; o > 0; o >>= 1) {
                a0 += __shfl_down_sync(0xffffffffu, a0, o);
                a1 += __shfl_down_sync(0xffffffffu, a1, o);
            }
            if (lane == 0) { sSc[0] = a0 + ba0; sSc[1] = a1 + ba1; }
        }
        // warp 6: pending merged writeback + prefetch stack[sp-3], enc[bp+1]
        if (warp == 6) {
            int lane = tid - 192;
            if (pendWp >= 0) {
                const float4* src = (const float4*)(sBuf + i0 * 200);
                for (int q = lane; q < 50; q += 32)
                    stcg4(&g_stk[pendWp * ENCD + 4 * q], src[q]);
            }
            float4* dpre = (float4*)(sBuf + ipre * 200);
            float4* dbn  = (float4*)(sBuf + ibn  * 200);
            const float4* mi4 = (const float4*)sMiss;
            for (int q = lane; q < 50; q += 32)
                dpre[q] = (sp >= 3) ? ldcg4(&g_stk[(sp - 3) * ENCD + 4 * q]) : mi4[q];
            int nbp = bp + 1;
            for (int q = lane; q < 50; q += 32)
                dbn[q] = (nbp < NSEQ) ? __ldg(((const float4*)(g_enc + nbp * ENCD)) + q)
                                      : mi4[q];
        }
        pendWp = -1;
        __syncthreads();

        // ==== PHASE B ====
        float m0 = (bp < NSEQ) ? sSc[0] : -1e30f;
        float m1 = (sp >= 2)   ? sSc[1] : -1e30f;
        bool is_shift = (m0 >= m1);   // argmax, first-index tie-break

        if (is_shift) {
            // push FULL b vector (CTA-redundant stack) — no cluster sync
            if (warp == 0 && tid < 25) {
                const float4* src = (const float4*)(sBuf + ib * 200);
                stcg4(&g_stk[sp * ENCD + 8 * tid],     src[2 * tid]);
                stcg4(&g_stk[sp * ENCD + 8 * tid + 4], src[2 * tid + 1]);
            }
            int t = i1; i1 = i0; i0 = ib; ib = ibn; ibn = t;
            sp += 1; bp += 1;
        } else {
            if (warp == 0) {
                if (tid < JC) {
                    int u = tid;
                    int j = jlo + u;
                    float gi = sG[u],          gf1 = sG[JC + u], gf2 = sG[2 * JC + u];
                    float go = sG[3 * JC + u], gu  = sG[4 * JC + u];
                    float c1 = sBuf[i1 * 200 + 100 + j];
                    float c2 = sBuf[i0 * 200 + 100 + j];
                    float c = sigf(gf1) * c1 + sigf(gf2) * c2 + sigf(gi) * tanh_acc(gu);
                    float h = sigf(go) * tanh_acc(c);
                    sBuf[isp * 200 + j]       = h;
                    sBuf[isp * 200 + 100 + j] = c;
                    unsigned int ah = sBufA + (unsigned int)(isp * 200 + j) * 4u;
                    unsigned int ac = sBufA + (unsigned int)(isp * 200 + 100 + j) * 4u;
#pragma unroll
                    for (unsigned int rk = 0; rk < PCLUSTER; rk++) {
                        if (rk != rank) { st_remote_f32(ah, rk, h); st_remote_f32(ac, rk, c); }
                    }
                }
                __syncwarp(0xffffffffu);
                if (tid < PCLUSTER) mbar_arrive_rank(mbarA, (unsigned int)tid);
            }
            mbar_wait_cta(mbarA, (unsigned int)rp);
            rp ^= 1;
            pendWp = sp - 2;           // merged -> g_stk next step (off path)
            int n1 = ipre, n0 = isp;
            ipre = i1; isp = i0;
            i1 = n1; i0 = n0;          // merged now at i0
            sp -= 1;
        }
    }

    // final stack[0] = last merged = sBuf[i0] (h | c)
    if (rank == 0 && tid < 200) out[tid] = sBuf[i0 * 200 + tid];
}

// ---------------------------------------------------------------------------
extern "C" void kernel_launch(void* const* d_in, const int* in_sizes, int n_in,
                              void* d_out, int out_size)
{
    const int*   tokens  = (const int*)d_in[0];
    const int*   lengths = (const int*)d_in[1];
    const float* emb     = (const float*)d_in[2];
    const float* Wih0    = (const float*)d_in[3];
    const float* Whh0    = (const float*)d_in[4];
    const float* b0      = (const float*)d_in[5];
    const float* Wih12   = (const float*)d_in[6];
    const float* Whh12   = (const float*)d_in[7];
    const float* b12     = (const float*)d_in[8];
    const float* missing = (const float*)d_in[9];
    const float* Wa      = (const float*)d_in[10];
    const float* ba      = (const float*)d_in[11];
    const float* Wt      = (const float*)d_in[12];
    const float* bt      = (const float*)d_in[13];
    float* out = (float*)d_out;

    float *P, *Ya, *Yb, *enc;
    cudaGetSymbolAddress((void**)&P,  g_P);
    cudaGetSymbolAddress((void**)&Ya, g_Ya);
    cudaGetSymbolAddress((void**)&Yb, g_Yb);
    cudaGetSymbolAddress((void**)&enc, g_enc);

    const int parsSmem = PRS_TOTAL * 4;                    // 75008
    cudaFuncSetAttribute(parser8, cudaFuncAttributeMaxDynamicSharedMemorySize, parsSmem);

    dim3 gg(64, 10), rg(64, 2);

    // layer 0
    proj_gemm<<<gg, 256>>>(emb, tokens, Wih0, b0, P, 300);
    lstm_rec<<<rg, 400>>>(P, Whh0, lengths, Ya, nullptr);
    // layer 1
    proj_gemm<<<gg, 256>>>(Ya, nullptr, Wih12, b12, P, 200);
    lstm_rec<<<rg, 400>>>(P, Whh12, lengths, Yb, nullptr);
    // layer 2 (+ fused meanpool -> enc)
    proj_gemm<<<gg, 256>>>(Yb, nullptr, Wih12 + 160000, b12 + 800, P, 200);
    lstm_rec<<<rg, 400>>>(P, Whh12 + 80000, lengths, nullptr, enc);
    // parse
    parser8<<<PCLUSTER, PR_THREADS, parsSmem>>>(missing, Wa, ba, Wt, bt, out);
}

// round 15
// speedup vs baseline: 1.0270x; 1.0199x over previous
#include <cuda_runtime.h>
#include <stdint.h>
#include <math.h>

#define NSEQ 256
#define TLEN 32
#define MROWS 8192      // NSEQ*TLEN
#define ENCD 200

// scratch (static device allocations are allowed)
__device__ float g_P  [MROWS * 800];
__device__ float g_Ya [MROWS * ENCD];
__device__ float g_Yb [MROWS * ENCD];
__device__ float g_enc[NSEQ * ENCD];
__device__ float g_stk[NSEQ * ENCD];

__device__ __forceinline__ float sigf(float x) { return 1.0f / (1.0f + expf(-x)); }
// accurate tanh via expf (robust even under fast-math)
__device__ __forceinline__ float tanh_acc(float x) {
    float e = expf(-2.0f * fabsf(x));
    float r = (1.0f - e) / (1.0f + e);
    return x >= 0.0f ? r : -r;
}
__device__ __forceinline__ float4 ldcg4(const float* p) {
    float4 v;
    asm volatile("ld.global.cg.v4.f32 {%0,%1,%2,%3}, [%4];"
                 : "=f"(v.x), "=f"(v.y), "=f"(v.z), "=f"(v.w) : "l"(p));
    return v;
}
__device__ __forceinline__ void stcg4(float* p, float4 v) {
    asm volatile("st.global.cg.v4.f32 [%0], {%1,%2,%3,%4};"
                 :: "l"(p), "f"(v.x), "f"(v.y), "f"(v.z), "f"(v.w));
}
__device__ __forceinline__ unsigned int smem_u32(const void* p) {
    unsigned int a;
    asm("{ .reg .u64 t; cvta.to.shared.u64 t, %1; cvt.u32.u64 %0, t; }"
        : "=r"(a) : "l"(p));
    return a;
}
__device__ __forceinline__ unsigned int ctarank() {
    unsigned int r; asm("mov.u32 %0, %%cluster_ctarank;" : "=r"(r)); return r;
}
__device__ __forceinline__ void st_remote_f32(unsigned int laddr, unsigned int rk, float v) {
    asm volatile(
        "{ .reg .b32 ra; mapa.shared::cluster.u32 ra, %0, %1; "
        "st.shared::cluster.f32 [ra], %2; }"
        :: "r"(laddr), "r"(rk), "f"(v) : "memory");
}
__device__ __forceinline__ void mbar_init(unsigned int addr, unsigned int count) {
    asm volatile("mbarrier.init.shared.b64 [%0], %1;" :: "r"(addr), "r"(count) : "memory");
}
// remote (or self) arrive, release.cluster semantics (default)
__device__ __forceinline__ void mbar_arrive_rank(unsigned int laddr, unsigned int rk) {
    asm volatile(
        "{ .reg .b32 ra; mapa.shared::cluster.u32 ra, %0, %1; "
        "mbarrier.arrive.shared::cluster.b64 _, [ra]; }"
        :: "r"(laddr), "r"(rk) : "memory");
}
// CTA-scope acquire wait (measured best)
__device__ __forceinline__ void mbar_wait_cta(unsigned int addr, unsigned int parity) {
    asm volatile(
        "{\n\t.reg .pred P1;\n\t"
        "WL%=:\n\t"
        "mbarrier.try_wait.parity.acquire.cta.shared::cta.b64 P1, [%0], %1, 0x989680;\n\t"
        "@P1 bra.uni WD%=;\n\t"
        "bra.uni WL%=;\n\t"
        "WD%=:\n\t}"
        :: "r"(addr), "r"(parity) : "memory");
}

// ---------------------------------------------------------------------------
// P[m][800] = A[row(m)][0:K] @ W[n][0:K]^T + bias[n]
// BM=128, BN=80, BK=20, 256 threads, 8x5 micro-tile
// ---------------------------------------------------------------------------
__global__ __launch_bounds__(256) void proj_gemm(
    const float* __restrict__ Asrc, const int* __restrict__ tok,
    const float* __restrict__ W, const float* __restrict__ bias,
    float* __restrict__ P, int K)
{
    __shared__ float As[20][132];   // k-major, 128 rows + 4 pad
    __shared__ float Ws[20][80];
    __shared__ long long roff[128];

    const int tid = threadIdx.x;
    const int M0 = blockIdx.x * 128;
    const int N0 = blockIdx.y * 80;

    if (tid < 128) {
        long long o = tok ? (long long)__ldg(&tok[M0 + tid]) * (long long)K
                          : (long long)(M0 + tid) * (long long)K;
        roff[tid] = o;
    }
    const int m0 = (tid >> 4) * 8;
    const int n0 = (tid & 15) * 5;

    float acc[8][5];
#pragma unroll
    for (int i = 0; i < 8; i++)
#pragma unroll
        for (int j = 0; j < 5; j++) acc[i][j] = 0.0f;
    __syncthreads();

    for (int kt = 0; kt < K; kt += 20) {
#pragma unroll
        for (int half = 0; half < 2; half++) {
            int i0 = (tid + half * 256) * 5;
            int mm = i0 / 20, kk = i0 % 20;
            const float* ap = Asrc + roff[mm] + kt + kk;
#pragma unroll
            for (int q = 0; q < 5; q++) As[kk + q][mm] = ap[q];
        }
        for (int i = tid; i < 1600; i += 256) {
            int nn = i / 20, kk = i % 20;
            Ws[kk][nn] = __ldg(&W[(size_t)(N0 + nn) * K + kt + kk]);
        }
        __syncthreads();
#pragma unroll
        for (int kk = 0; kk < 20; kk++) {
            float4 a4lo = *(const float4*)&As[kk][m0];
            float4 a4hi = *(const float4*)&As[kk][m0 + 4];
            float a[8] = {a4lo.x, a4lo.y, a4lo.z, a4lo.w,
                          a4hi.x, a4hi.y, a4hi.z, a4hi.w};
            float b[5];
#pragma unroll
            for (int j = 0; j < 5; j++) b[j] = Ws[kk][n0 + j];
#pragma unroll
            for (int i = 0; i < 8; i++)
#pragma unroll
                for (int j = 0; j < 5; j++) acc[i][j] += a[i] * b[j];
        }
        __syncthreads();
    }
#pragma unroll
    for (int i = 0; i < 8; i++) {
        size_t row = (size_t)(M0 + m0 + i) * 800 + N0 + n0;
#pragma unroll
        for (int j = 0; j < 5; j++)
            P[row + j] = acc[i][j] + __ldg(&bias[N0 + n0 + j]);
    }
}

// ---------------------------------------------------------------------------
// LSTM recurrence: Whh register-resident (measured best).
// If encOut != null, fuse mean-pool, skip Y.
// ---------------------------------------------------------------------------
__global__ __launch_bounds__(400, 1) void lstm_rec(
    const float* __restrict__ P, const float* __restrict__ Whh2,
    const int* __restrict__ lengths, float* __restrict__ Y,
    float* __restrict__ encOut)
{
    __shared__ float sH[400];
    __shared__ float sC[400];
    __shared__ float sG[1600];

    const int tid = threadIdx.x;
    const int dir = blockIdx.y;
    const int sq0 = blockIdx.x * 4;

    float4 w[25];
    {
        const float4* wg = (const float4*)(Whh2 + dir * 40000 + tid * 100);
#pragma unroll
        for (int q = 0; q < 25; q++) w[q] = __ldg(&wg[q]);
    }

    if (tid < 400) { sH[tid] = 0.0f; sC[tid] = 0.0f; }

    const int sPW = tid / 100;
    const int jPW = tid % 100;
    const int myLen = __ldg(&lengths[sq0 + sPW]);
    __syncthreads();

    const float4* sH4 = (const float4*)sH;

    float p0, p1, p2, p3;
    {
        int t = dir ? (TLEN - 1) : 0;
        size_t base = ((size_t)sq0 * TLEN + t) * 800 + dir * 400 + tid;
        p0 = __ldg(&P[base]);
        p1 = __ldg(&P[base + 1 * TLEN * 800]);
        p2 = __ldg(&P[base + 2 * TLEN * 800]);
        p3 = __ldg(&P[base + 3 * TLEN * 800]);
    }
    float hsum = 0.0f;

    for (int st = 0; st < TLEN; st++) {
        int t = dir ? (TLEN - 1 - st) : st;
        float acc0 = p0, acc1 = p1, acc2 = p2, acc3 = p3;
        if (st + 1 < TLEN) {
            int tn = dir ? (TLEN - 2 - st) : (st + 1);
            size_t base = ((size_t)sq0 * TLEN + tn) * 800 + dir * 400 + tid;
            p0 = __ldg(&P[base]);
            p1 = __ldg(&P[base + 1 * TLEN * 800]);
            p2 = __ldg(&P[base + 2 * TLEN * 800]);
            p3 = __ldg(&P[base + 3 * TLEN * 800]);
        }
#pragma unroll
        for (int kq = 0; kq < 25; kq++) {
            float4 wq = w[kq];
            float4 h0 = sH4[kq], h1 = sH4[25 + kq], h2 = sH4[50 + kq], h3 = sH4[75 + kq];
            acc0 += wq.x * h0.x + wq.y * h0.y + wq.z * h0.z + wq.w * h0.w;
            acc1 += wq.x * h1.x + wq.y * h1.y + wq.z * h1.z + wq.w * h1.w;
            acc2 += wq.x * h2.x + wq.y * h2.y + wq.z * h2.z + wq.w * h2.w;
            acc3 += wq.x * h3.x + wq.y * h3.y + wq.z * h3.z + wq.w * h3.w;
        }
        sG[tid] = acc0; sG[400 + tid] = acc1; sG[800 + tid] = acc2; sG[1200 + tid] = acc3;
        __syncthreads();
        {
            float gi = sG[sPW * 400 + jPW];
            float gf = sG[sPW * 400 + 100 + jPW];
            float gg = sG[sPW * 400 + 200 + jPW];
            float go = sG[sPW * 400 + 300 + jPW];
            float c  = sC[sPW * 100 + jPW];
            float cn = sigf(gf) * c + sigf(gi) * tanh_acc(gg);
            float hn = sigf(go) * tanh_acc(cn);
            float outv = 0.0f;
            if (t < myLen) {
                sC[sPW * 100 + jPW] = cn;
                sH[sPW * 100 + jPW] = hn;
                outv = hn;
            }
            if (encOut) hsum += outv;
            else Y[((size_t)(sq0 + sPW) * TLEN + t) * ENCD + dir * 100 + jPW] = outv;
        }
        __syncthreads();
    }
    if (encOut)
        encOut[(sq0 + sPW) * ENCD + dir * 100 + jPW] = hsum / (float)myLen;
}

// ---------------------------------------------------------------------------
// Parser: 8-CTA cluster, barrier only on reduce steps + NEW: 32-row smem
// stack ring (tagged). Prefetch of stack[sp-3] becomes an smem copy on ring
// hit (g_stk kept as dual-written fallback for rare evictions).
// ---------------------------------------------------------------------------
#define PRS_WT    0          // 16000
#define PRS_WA    16000      // 1200
#define PRS_BT    17200      // 72
#define PRS_BUF   17272      // 1200
#define PRS_G     18472      // 72
#define PRS_MISS  18544      // 200
#define PRS_SC    18744      // 2
#define PRS_MBAR  18748      // 2 (8B aligned)
#define PRS_RING  18752      // 32*200 = 6400
#define PRS_TAG   25152      // 32 ints
#define PRS_TOTAL 25184
#define PR_THREADS 224
#define PCLUSTER 8
#define RING_SZ 32

__global__ __cluster_dims__(PCLUSTER, 1, 1) __launch_bounds__(PR_THREADS, 1) void parser8(
    const float* __restrict__ missing, const float* __restrict__ Wa,
    const float* __restrict__ ba, const float* __restrict__ Wt,
    const float* __restrict__ bt, float* __restrict__ out)
{
    extern __shared__ float sm[];
    float* sWt   = sm + PRS_WT;
    float* sWa   = sm + PRS_WA;
    float* sBt   = sm + PRS_BT;
    float* sBuf  = sm + PRS_BUF;
    float* sG    = sm + PRS_G;
    float* sMiss = sm + PRS_MISS;
    float* sSc   = sm + PRS_SC;
    float* sRing = sm + PRS_RING;
    int*   sTagA = (int*)(sm + PRS_TAG);
    const int tid = threadIdx.x;
    const unsigned int rank = ctarank();
    const int JC  = ((int)rank < 4) ? 13 : 12;          // units owned
    const int jlo = (int)rank * 12 + (((int)rank < 4) ? (int)rank : 4);
    const int NR  = 5 * JC;                              // gate rows owned
    const unsigned int mbarA = smem_u32(sm + PRS_MBAR);
    const unsigned int sBufA = smem_u32(sBuf);

    // Wt rows warp-coalesced (round-12 layout, measured-neutral but kept)
    for (int i = tid; i < NR * 200; i += PR_THREADS) {
        int r = i / 200, k = i - r * 200;
        int ph = k / 100, kk = k - ph * 100;
        int q = kk >> 2, e = kk & 3;
        int wt = 2 * r + ph;
        int slot = (((wt >> 5) * 25 + q) * 32 + (wt & 31)) * 4 + e;
        int grow = (r / JC) * 100 + jlo + (r % JC);
        sWt[slot] = __ldg(&Wt[grow * 200 + k]);
    }
    for (int i = tid; i < 1200; i += PR_THREADS) sWa[i] = __ldg(&Wa[i]);
    if (tid < NR) {
        int grow = (tid / JC) * 100 + jlo + (tid % JC);
        sBt[tid] = __ldg(&bt[grow]);
    }
    if (tid < 200) {
        float mv = __ldg(&missing[tid]);
        sMiss[tid] = mv;
        sBuf[0 * 200 + tid] = mv;                    // i1 = missing
        sBuf[1 * 200 + tid] = mv;                    // i0 = missing
        sBuf[2 * 200 + tid] = __ldg(&g_enc[tid]);    // ib = enc[0]
    }
    if (tid < RING_SZ) sTagA[tid] = -1;
    const float ba0 = __ldg(&ba[0]), ba1 = __ldg(&ba[1]);
    if (tid == 0) mbar_init(mbarA, PCLUSTER);
    __syncthreads();
    asm volatile("barrier.cluster.arrive.aligned;" ::: "memory");
    asm volatile("barrier.cluster.wait.aligned;"   ::: "memory");

    int i1 = 0, i0 = 1, ib = 2, ipre = 3, ibn = 4, isp = 5;
    int sp = 0, bp = 0;
    int rp = 0;                // reduce parity
    int pendWp = -1;           // pending merged -> ring/g_stk writeback row
    const int warp = tid >> 5;

    for (int step = 0; step < 2 * NSEQ - 1; step++) {
        // ==== PHASE A: all independent work in parallel ====
        // warps 0-4: speculative gate GEMV (warp-coalesced Wt)
        if (tid < 2 * NR) {
            int ph = tid & 1;
            const float4* wp4 = (const float4*)sWt + ((tid >> 5) * 25) * 32 + (tid & 31);
            const float4* xp  = (const float4*)(sBuf + (ph ? i0 : i1) * 200);
            float acc = 0.0f;
#pragma unroll
            for (int q = 0; q < 25; q++) {
                float4 w = wp4[q * 32];
                float4 x = xp[q];
                acc += w.x * x.x + w.y * x.y + w.z * x.z + w.w * x.w;
            }
            unsigned msk = __activemask();
            acc += __shfl_xor_sync(msk, acc, 1);
            if (!ph) sG[tid >> 1] = acc + sBt[tid >> 1];
        }
        // warp 5: score GEMV (replicated in every CTA)
        if (warp == 5) {
            int lane = tid - 160;
            const float* w0 = sWa;
            const float* w1 = sWa + 600;
            const float* f1p = sBuf + i1 * 200;
            const float* f0p = sBuf + i0 * 200;
            const float* fbp = sBuf + ib * 200;
            float a0 = 0.0f, a1 = 0.0f;
#pragma unroll
            for (int k = 0; k < 7; k++) {
                int kk = lane + 32 * k;
                if (kk < 200) { float f = f1p[kk]; a0 += w0[kk] * f;       a1 += w1[kk] * f; }
            }
#pragma unroll
            for (int k = 0; k < 7; k++) {
                int kk = lane + 32 * k;
                if (kk < 200) { float f = f0p[kk]; a0 += w0[200 + kk] * f; a1 += w1[200 + kk] * f; }
            }
#pragma unroll
            for (int k = 0; k < 7; k++) {
                int kk = lane + 32 * k;
                if (kk < 200) { float f = fbp[kk]; a0 += w0[400 + kk] * f; a1 += w1[400 + kk] * f; }
            }
#pragma unroll
            for (int o = 16; o > 0; o >>= 1) {
                a0 += __shfl_down_sync(0xffffffffu, a0, o);
                a1 += __shfl_down_sync(0xffffffffu, a1, o);
            }
            if (lane == 0) { sSc[0] = a0 + ba0; sSc[1] = a1 + ba1; }
        }
        // warp 6: pending merged writeback (ring+global) + prefetches
        if (warp == 6) {
            int lane = tid - 192;
            if (pendWp >= 0) {
                int slot = pendWp & (RING_SZ - 1);
                const float4* src = (const float4*)(sBuf + i0 * 200);
                float4* rdst = (float4*)(sRing + slot * 200);
                for (int q = lane; q < 50; q += 32) {
                    float4 v = src[q];
                    rdst[q] = v;
                    stcg4(&g_stk[pendWp * ENCD + 4 * q], v);
                }
                if (lane == 0) sTagA[slot] = pendWp;
            }
            // prefetch stack[sp-3] -> ipre (ring hit = smem copy)
            float4* dpre = (float4*)(sBuf + ipre * 200);
            const float4* mi4 = (const float4*)sMiss;
            int r = sp - 3;
            if (r >= 0) {
                int slot = r & (RING_SZ - 1);
                if (sTagA[slot] == r) {
                    const float4* rs = (const float4*)(sRing + slot * 200);
                    for (int q = lane; q < 50; q += 32) dpre[q] = rs[q];
                } else {
                    for (int q = lane; q < 50; q += 32)
                        dpre[q] = ldcg4(&g_stk[r * ENCD + 4 * q]);
                }
            } else {
                for (int q = lane; q < 50; q += 32) dpre[q] = mi4[q];
            }
            // prefetch enc[bp+1] -> ibn
            float4* dbn = (float4*)(sBuf + ibn * 200);
            int nbp = bp + 1;
            for (int q = lane; q < 50; q += 32)
                dbn[q] = (nbp < NSEQ) ? __ldg(((const float4*)(g_enc + nbp * ENCD)) + q)
                                      : mi4[q];
        }
        pendWp = -1;
        __syncthreads();

        // ==== PHASE B ====
        float m0 = (bp < NSEQ) ? sSc[0] : -1e30f;
        float m1 = (sp >= 2)   ? sSc[1] : -1e30f;
        bool is_shift = (m0 >= m1);   // argmax, first-index tie-break

        if (is_shift) {
            // push FULL b vector: ring + global (CTA-redundant) — no sync
            if (warp == 0 && tid < 25) {
                int slot = sp & (RING_SZ - 1);
                const float4* src = (const float4*)(sBuf + ib * 200);
                float4* rdst = (float4*)(sRing + slot * 200);
                float4 v0 = src[2 * tid], v1 = src[2 * tid + 1];
                rdst[2 * tid] = v0; rdst[2 * tid + 1] = v1;
                stcg4(&g_stk[sp * ENCD + 8 * tid],     v0);
                stcg4(&g_stk[sp * ENCD + 8 * tid + 4], v1);
                if (tid == 0) sTagA[slot] = sp;
            }
            int t = i1; i1 = i0; i0 = ib; ib = ibn; ibn = t;
            sp += 1; bp += 1;
        } else {
            if (warp == 0) {
                if (tid < JC) {
                    int u = tid;
                    int j = jlo + u;
                    float gi = sG[u],          gf1 = sG[JC + u], gf2 = sG[2 * JC + u];
                    float go = sG[3 * JC + u], gu  = sG[4 * JC + u];
                    float c1 = sBuf[i1 * 200 + 100 + j];
                    float c2 = sBuf[i0 * 200 + 100 + j];
                    float c = sigf(gf1) * c1 + sigf(gf2) * c2 + sigf(gi) * tanh_acc(gu);
                    float h = sigf(go) * tanh_acc(c);
                    sBuf[isp * 200 + j]       = h;
                    sBuf[isp * 200 + 100 + j] = c;
                    unsigned int ah = sBufA + (unsigned int)(isp * 200 + j) * 4u;
                    unsigned int ac = sBufA + (unsigned int)(isp * 200 + 100 + j) * 4u;
#pragma unroll
                    for (unsigned int rk = 0; rk < PCLUSTER; rk++) {
                        if (rk != rank) { st_remote_f32(ah, rk, h); st_remote_f32(ac, rk, c); }
                    }
                }
                __syncwarp(0xffffffffu);
                if (tid < PCLUSTER) mbar_arrive_rank(mbarA, (unsigned int)tid);
            }
            mbar_wait_cta(mbarA, (unsigned int)rp);
            rp ^= 1;
            pendWp = sp - 2;           // merged -> ring/g_stk next step
            int n1 = ipre, n0 = isp;
            ipre = i1; isp = i0;
            i1 = n1; i0 = n0;          // merged now at i0
            sp -= 1;
        }
    }

    // final stack[0] = last merged = sBuf[i0] (h | c)
    if (rank == 0 && tid < 200) out[tid] = sBuf[i0 * 200 + tid];
}

// ---------------------------------------------------------------------------
extern "C" void kernel_launch(void* const* d_in, const int* in_sizes, int n_in,
                              void* d_out, int out_size)
{
    const int*   tokens  = (const int*)d_in[0];
    const int*   lengths = (const int*)d_in[1];
    const float* emb     = (const float*)d_in[2];
    const float* Wih0    = (const float*)d_in[3];
    const float* Whh0    = (const float*)d_in[4];
    const float* b0      = (const float*)d_in[5];
    const float* Wih12   = (const float*)d_in[6];
    const float* Whh12   = (const float*)d_in[7];
    const float* b12     = (const float*)d_in[8];
    const float* missing = (const float*)d_in[9];
    const float* Wa      = (const float*)d_in[10];
    const float* ba      = (const float*)d_in[11];
    const float* Wt      = (const float*)d_in[12];
    const float* bt      = (const float*)d_in[13];
    float* out = (float*)d_out;

    float *P, *Ya, *Yb, *enc;
    cudaGetSymbolAddress((void**)&P,  g_P);
    cudaGetSymbolAddress((void**)&Ya, g_Ya);
    cudaGetSymbolAddress((void**)&Yb, g_Yb);
    cudaGetSymbolAddress((void**)&enc, g_enc);

    const int parsSmem = PRS_TOTAL * 4;                    // 100736
    cudaFuncSetAttribute(parser8, cudaFuncAttributeMaxDynamicSharedMemorySize, parsSmem);

    dim3 gg(64, 10), rg(64, 2);

    // layer 0
    proj_gemm<<<gg, 256>>>(emb, tokens, Wih0, b0, P, 300);
    lstm_rec<<<rg, 400>>>(P, Whh0, lengths, Ya, nullptr);
    // layer 1
    proj_gemm<<<gg, 256>>>(Ya, nullptr, Wih12, b12, P, 200);
    lstm_rec<<<rg, 400>>>(P, Whh12, lengths, Yb, nullptr);
    // layer 2 (+ fused meanpool -> enc)
    proj_gemm<<<gg, 256>>>(Yb, nullptr, Wih12 + 160000, b12 + 800, P, 200);
    lstm_rec<<<rg, 400>>>(P, Whh12 + 80000, lengths, nullptr, enc);
    // parse
    parser8<<<PCLUSTER, PR_THREADS, parsSmem>>>(missing, Wa, ba, Wt, bt, out);
}

// round 17
// speedup vs baseline: 1.1223x; 1.0927x over previous
#include <cuda_runtime.h>
#include <stdint.h>
#include <math.h>

#define NSEQ 256
#define TLEN 32
#define MROWS 8192      // NSEQ*TLEN
#define ENCD 200

// scratch (static device allocations are allowed)
__device__ float g_P  [MROWS * 800];
__device__ float g_Ya [MROWS * ENCD];
__device__ float g_Yb [MROWS * ENCD];
__device__ float g_enc[NSEQ * ENCD];
__device__ float g_stk[NSEQ * ENCD];

__device__ __forceinline__ float sigf(float x) { return 1.0f / (1.0f + expf(-x)); }
// accurate tanh via expf (robust even under fast-math)
__device__ __forceinline__ float tanh_acc(float x) {
    float e = expf(-2.0f * fabsf(x));
    float r = (1.0f - e) / (1.0f + e);
    return x >= 0.0f ? r : -r;
}
__device__ __forceinline__ float4 ldcg4(const float* p) {
    float4 v;
    asm volatile("ld.global.cg.v4.f32 {%0,%1,%2,%3}, [%4];"
                 : "=f"(v.x), "=f"(v.y), "=f"(v.z), "=f"(v.w) : "l"(p));
    return v;
}
__device__ __forceinline__ void stcg4(float* p, float4 v) {
    asm volatile("st.global.cg.v4.f32 [%0], {%1,%2,%3,%4};"
                 :: "l"(p), "f"(v.x), "f"(v.y), "f"(v.z), "f"(v.w));
}
__device__ __forceinline__ unsigned int smem_u32(const void* p) {
    unsigned int a;
    asm("{ .reg .u64 t; cvta.to.shared.u64 t, %1; cvt.u32.u64 %0, t; }"
        : "=r"(a) : "l"(p));
    return a;
}
__device__ __forceinline__ unsigned int ctarank() {
    unsigned int r; asm("mov.u32 %0, %%cluster_ctarank;" : "=r"(r)); return r;
}
__device__ __forceinline__ void st_remote_f32(unsigned int laddr, unsigned int rk, float v) {
    asm volatile(
        "{ .reg .b32 ra; mapa.shared::cluster.u32 ra, %0, %1; "
        "st.shared::cluster.f32 [ra], %2; }"
        :: "r"(laddr), "r"(rk), "f"(v) : "memory");
}
__device__ __forceinline__ void mbar_init(unsigned int addr, unsigned int count) {
    asm volatile("mbarrier.init.shared.b64 [%0], %1;" :: "r"(addr), "r"(count) : "memory");
}
// remote (or self) arrive, release.cluster semantics (default)
__device__ __forceinline__ void mbar_arrive_rank(unsigned int laddr, unsigned int rk) {
    asm volatile(
        "{ .reg .b32 ra; mapa.shared::cluster.u32 ra, %0, %1; "
        "mbarrier.arrive.shared::cluster.b64 _, [ra]; }"
        :: "r"(laddr), "r"(rk) : "memory");
}
// CTA-scope acquire wait (measured best)
__device__ __forceinline__ void mbar_wait_cta(unsigned int addr, unsigned int parity) {
    asm volatile(
        "{\n\t.reg .pred P1;\n\t"
        "WL%=:\n\t"
        "mbarrier.try_wait.parity.acquire.cta.shared::cta.b64 P1, [%0], %1, 0x989680;\n\t"
        "@P1 bra.uni WD%=;\n\t"
        "bra.uni WL%=;\n\t"
        "WD%=:\n\t}"
        :: "r"(addr), "r"(parity) : "memory");
}

// ---------------------------------------------------------------------------
// P[m][800] = A[row(m)][0:K] @ W[n][0:K]^T + bias[n]
// BM=128, BN=80, BK=20, 256 threads, 8x5 micro-tile
// ---------------------------------------------------------------------------
__global__ __launch_bounds__(256) void proj_gemm(
    const float* __restrict__ Asrc, const int* __restrict__ tok,
    const float* __restrict__ W, const float* __restrict__ bias,
    float* __restrict__ P, int K)
{
    __shared__ float As[20][132];   // k-major, 128 rows + 4 pad
    __shared__ float Ws[20][80];
    __shared__ long long roff[128];

    const int tid = threadIdx.x;
    const int M0 = blockIdx.x * 128;
    const int N0 = blockIdx.y * 80;

    if (tid < 128) {
        long long o = tok ? (long long)__ldg(&tok[M0 + tid]) * (long long)K
                          : (long long)(M0 + tid) * (long long)K;
        roff[tid] = o;
    }
    const int m0 = (tid >> 4) * 8;
    const int n0 = (tid & 15) * 5;

    float acc[8][5];
#pragma unroll
    for (int i = 0; i < 8; i++)
#pragma unroll
        for (int j = 0; j < 5; j++) acc[i][j] = 0.0f;
    __syncthreads();

    for (int kt = 0; kt < K; kt += 20) {
#pragma unroll
        for (int half = 0; half < 2; half++) {
            int i0 = (tid + half * 256) * 5;
            int mm = i0 / 20, kk = i0 % 20;
            const float* ap = Asrc + roff[mm] + kt + kk;
#pragma unroll
            for (int q = 0; q < 5; q++) As[kk + q][mm] = ap[q];
        }
        for (int i = tid; i < 1600; i += 256) {
            int nn = i / 20, kk = i % 20;
            Ws[kk][nn] = __ldg(&W[(size_t)(N0 + nn) * K + kt + kk]);
        }
        __syncthreads();
#pragma unroll
        for (int kk = 0; kk < 20; kk++) {
            float4 a4lo = *(const float4*)&As[kk][m0];
            float4 a4hi = *(const float4*)&As[kk][m0 + 4];
            float a[8] = {a4lo.x, a4lo.y, a4lo.z, a4lo.w,
                          a4hi.x, a4hi.y, a4hi.z, a4hi.w};
            float b[5];
#pragma unroll
            for (int j = 0; j < 5; j++) b[j] = Ws[kk][n0 + j];
#pragma unroll
            for (int i = 0; i < 8; i++)
#pragma unroll
                for (int j = 0; j < 5; j++) acc[i][j] += a[i] * b[j];
        }
        __syncthreads();
    }
#pragma unroll
    for (int i = 0; i < 8; i++) {
        size_t row = (size_t)(M0 + m0 + i) * 800 + N0 + n0;
#pragma unroll
        for (int j = 0; j < 5; j++)
            P[row + j] = acc[i][j] + __ldg(&bias[N0 + n0 + j]);
    }
}

// ---------------------------------------------------------------------------
// LSTM recurrence: Whh register-resident (measured best).
// If encOut != null, fuse mean-pool, skip Y.
// ---------------------------------------------------------------------------
__global__ __launch_bounds__(400, 1) void lstm_rec(
    const float* __restrict__ P, const float* __restrict__ Whh2,
    const int* __restrict__ lengths, float* __restrict__ Y,
    float* __restrict__ encOut)
{
    __shared__ float sH[400];
    __shared__ float sC[400];
    __shared__ float sG[1600];

    const int tid = threadIdx.x;
    const int dir = blockIdx.y;
    const int sq0 = blockIdx.x * 4;

    float4 w[25];
    {
        const float4* wg = (const float4*)(Whh2 + dir * 40000 + tid * 100);
#pragma unroll
        for (int q = 0; q < 25; q++) w[q] = __ldg(&wg[q]);
    }

    if (tid < 400) { sH[tid] = 0.0f; sC[tid] = 0.0f; }

    const int sPW = tid / 100;
    const int jPW = tid % 100;
    const int myLen = __ldg(&lengths[sq0 + sPW]);
    __syncthreads();

    const float4* sH4 = (const float4*)sH;

    float p0, p1, p2, p3;
    {
        int t = dir ? (TLEN - 1) : 0;
        size_t base = ((size_t)sq0 * TLEN + t) * 800 + dir * 400 + tid;
        p0 = __ldg(&P[base]);
        p1 = __ldg(&P[base + 1 * TLEN * 800]);
        p2 = __ldg(&P[base + 2 * TLEN * 800]);
        p3 = __ldg(&P[base + 3 * TLEN * 800]);
    }
    float hsum = 0.0f;

    for (int st = 0; st < TLEN; st++) {
        int t = dir ? (TLEN - 1 - st) : st;
        float acc0 = p0, acc1 = p1, acc2 = p2, acc3 = p3;
        if (st + 1 < TLEN) {
            int tn = dir ? (TLEN - 2 - st) : (st + 1);
            size_t base = ((size_t)sq0 * TLEN + tn) * 800 + dir * 400 + tid;
            p0 = __ldg(&P[base]);
            p1 = __ldg(&P[base + 1 * TLEN * 800]);
            p2 = __ldg(&P[base + 2 * TLEN * 800]);
            p3 = __ldg(&P[base + 3 * TLEN * 800]);
        }
#pragma unroll
        for (int kq = 0; kq < 25; kq++) {
            float4 wq = w[kq];
            float4 h0 = sH4[kq], h1 = sH4[25 + kq], h2 = sH4[50 + kq], h3 = sH4[75 + kq];
            acc0 += wq.x * h0.x + wq.y * h0.y + wq.z * h0.z + wq.w * h0.w;
            acc1 += wq.x * h1.x + wq.y * h1.y + wq.z * h1.z + wq.w * h1.w;
            acc2 += wq.x * h2.x + wq.y * h2.y + wq.z * h2.z + wq.w * h2.w;
            acc3 += wq.x * h3.x + wq.y * h3.y + wq.z * h3.z + wq.w * h3.w;
        }
        sG[tid] = acc0; sG[400 + tid] = acc1; sG[800 + tid] = acc2; sG[1200 + tid] = acc3;
        __syncthreads();
        {
            float gi = sG[sPW * 400 + jPW];
            float gf = sG[sPW * 400 + 100 + jPW];
            float gg = sG[sPW * 400 + 200 + jPW];
            float go = sG[sPW * 400 + 300 + jPW];
            float c  = sC[sPW * 100 + jPW];
            float cn = sigf(gf) * c + sigf(gi) * tanh_acc(gg);
            float hn = sigf(go) * tanh_acc(cn);
            float outv = 0.0f;
            if (t < myLen) {
                sC[sPW * 100 + jPW] = cn;
                sH[sPW * 100 + jPW] = hn;
                outv = hn;
            }
            if (encOut) hsum += outv;
            else Y[((size_t)(sq0 + sPW) * TLEN + t) * ENCD + dir * 100 + jPW] = outv;
        }
        __syncthreads();
    }
    if (encOut)
        encOut[(sq0 + sPW) * ENCD + dir * 100 + jPW] = hsum / (float)myLen;
}

// ---------------------------------------------------------------------------
// Parser: 8-CTA cluster, barrier only on reduce steps, 32-row smem stack
// ring + NEW: register-buffered enc prefetch (warp 6 never stalls on an
// LDG->STS chain inside a step; the STS uses data loaded >=1 step earlier).
// ---------------------------------------------------------------------------
#define PRS_WT    0          // 16000
#define PRS_WA    16000      // 1200
#define PRS_BT    17200      // 72
#define PRS_BUF   17272      // 1200
#define PRS_G     18472      // 72
#define PRS_MISS  18544      // 200
#define PRS_SC    18744      // 2
#define PRS_MBAR  18748      // 2 (8B aligned)
#define PRS_RING  18752      // 32*200 = 6400
#define PRS_TAG   25152      // 32 ints
#define PRS_TOTAL 25184
#define PR_THREADS 224
#define PCLUSTER 8
#define RING_SZ 32

__global__ __cluster_dims__(PCLUSTER, 1, 1) __launch_bounds__(PR_THREADS, 1) void parser8(
    const float* __restrict__ missing, const float* __restrict__ Wa,
    const float* __restrict__ ba, const float* __restrict__ Wt,
    const float* __restrict__ bt, float* __restrict__ out)
{
    extern __shared__ float sm[];
    float* sWt   = sm + PRS_WT;
    float* sWa   = sm + PRS_WA;
    float* sBt   = sm + PRS_BT;
    float* sBuf  = sm + PRS_BUF;
    float* sG    = sm + PRS_G;
    float* sMiss = sm + PRS_MISS;
    float* sSc   = sm + PRS_SC;
    float* sRing = sm + PRS_RING;
    int*   sTagA = (int*)(sm + PRS_TAG);
    const int tid = threadIdx.x;
    const unsigned int rank = ctarank();
    const int JC  = ((int)rank < 4) ? 13 : 12;          // units owned
    const int jlo = (int)rank * 12 + (((int)rank < 4) ? (int)rank : 4);
    const int NR  = 5 * JC;                              // gate rows owned
    const unsigned int mbarA = smem_u32(sm + PRS_MBAR);
    const unsigned int sBufA = smem_u32(sBuf);

    // Wt rows warp-coalesced
    for (int i = tid; i < NR * 200; i += PR_THREADS) {
        int r = i / 200, k = i - r * 200;
        int ph = k / 100, kk = k - ph * 100;
        int q = kk >> 2, e = kk & 3;
        int wt = 2 * r + ph;
        int slot = (((wt >> 5) * 25 + q) * 32 + (wt & 31)) * 4 + e;
        int grow = (r / JC) * 100 + jlo + (r % JC);
        sWt[slot] = __ldg(&Wt[grow * 200 + k]);
    }
    for (int i = tid; i < 1200; i += PR_THREADS) sWa[i] = __ldg(&Wa[i]);
    if (tid < NR) {
        int grow = (tid / JC) * 100 + jlo + (tid % JC);
        sBt[tid] = __ldg(&bt[grow]);
    }
    if (tid < 200) {
        float mv = __ldg(&missing[tid]);
        sMiss[tid] = mv;
        sBuf[0 * 200 + tid] = mv;                    // i1 = missing
        sBuf[1 * 200 + tid] = mv;                    // i0 = missing
        sBuf[2 * 200 + tid] = __ldg(&g_enc[tid]);            // ib  = enc[0]
        sBuf[4 * 200 + tid] = __ldg(&g_enc[ENCD + tid]);     // ibn = enc[1]
    }
    if (tid < RING_SZ) sTagA[tid] = -1;
    const float ba0 = __ldg(&ba[0]), ba1 = __ldg(&ba[1]);
    if (tid == 0) mbar_init(mbarA, PCLUSTER);

    // warp-6 register prefetch buffer: pf = enc[2]
    float4 pf0 = make_float4(0.f, 0.f, 0.f, 0.f);
    float4 pf1 = pf0;
    {
        int lane = tid - 192;
        if (lane >= 0 && lane < 32) {
            const float4* ep = (const float4*)(g_enc + 2 * ENCD);
            pf0 = __ldg(&ep[lane]);
            if (lane < 18) pf1 = __ldg(&ep[lane + 32]);
        }
    }
    __syncthreads();
    asm volatile("barrier.cluster.arrive.aligned;" ::: "memory");
    asm volatile("barrier.cluster.wait.aligned;"   ::: "memory");

    int i1 = 0, i0 = 1, ib = 2, ipre = 3, ibn = 4, isp = 5;
    int sp = 0, bp = 0;
    int rp = 0;                // reduce parity
    int pendWp = -1;           // pending merged -> ring/g_stk writeback row
    bool lastShift = false;
    const int warp = tid >> 5;

    for (int step = 0; step < 2 * NSEQ - 1; step++) {
        // ==== PHASE A: all independent work in parallel ====
        // warps 0-4: speculative gate GEMV (warp-coalesced Wt)
        if (tid < 2 * NR) {
            int ph = tid & 1;
            const float4* wp4 = (const float4*)sWt + ((tid >> 5) * 25) * 32 + (tid & 31);
            const float4* xp  = (const float4*)(sBuf + (ph ? i0 : i1) * 200);
            float acc = 0.0f;
#pragma unroll
            for (int q = 0; q < 25; q++) {
                float4 w = wp4[q * 32];
                float4 x = xp[q];
                acc += w.x * x.x + w.y * x.y + w.z * x.z + w.w * x.w;
            }
            unsigned msk = __activemask();
            acc += __shfl_xor_sync(msk, acc, 1);
            if (!ph) sG[tid >> 1] = acc + sBt[tid >> 1];
        }
        // warp 5: score GEMV (replicated in every CTA)
        if (warp == 5) {
            int lane = tid - 160;
            const float* w0 = sWa;
            const float* w1 = sWa + 600;
            const float* f1p = sBuf + i1 * 200;
            const float* f0p = sBuf + i0 * 200;
            const float* fbp = sBuf + ib * 200;
            float a0 = 0.0f, a1 = 0.0f;
#pragma unroll
            for (int k = 0; k < 7; k++) {
                int kk = lane + 32 * k;
                if (kk < 200) { float f = f1p[kk]; a0 += w0[kk] * f;       a1 += w1[kk] * f; }
            }
#pragma unroll
            for (int k = 0; k < 7; k++) {
                int kk = lane + 32 * k;
                if (kk < 200) { float f = f0p[kk]; a0 += w0[200 + kk] * f; a1 += w1[200 + kk] * f; }
            }
#pragma unroll
            for (int k = 0; k < 7; k++) {
                int kk = lane + 32 * k;
                if (kk < 200) { float f = fbp[kk]; a0 += w0[400 + kk] * f; a1 += w1[400 + kk] * f; }
            }
#pragma unroll
            for (int o = 16; o > 0; o >>= 1) {
                a0 += __shfl_down_sync(0xffffffffu, a0, o);
                a1 += __shfl_down_sync(0xffffffffu, a1, o);
            }
            if (lane == 0) { sSc[0] = a0 + ba0; sSc[1] = a1 + ba1; }
        }
        // warp 6: writeback + stack-ring prefetch + register-buffered enc
        if (warp == 6) {
            int lane = tid - 192;
            if (pendWp >= 0) {
                int slot = pendWp & (RING_SZ - 1);
                const float4* src = (const float4*)(sBuf + i0 * 200);
                float4* rdst = (float4*)(sRing + slot * 200);
                for (int q = lane; q < 50; q += 32) {
                    float4 v = src[q];
                    rdst[q] = v;
                    stcg4(&g_stk[pendWp * ENCD + 4 * q], v);
                }
                if (lane == 0) sTagA[slot] = pendWp;
            }
            // prefetch stack[sp-3] -> ipre (ring hit = smem copy)
            float4* dpre = (float4*)(sBuf + ipre * 200);
            const float4* mi4 = (const float4*)sMiss;
            int r = sp - 3;
            if (r >= 0) {
                int slot = r & (RING_SZ - 1);
                if (sTagA[slot] == r) {
                    const float4* rs = (const float4*)(sRing + slot * 200);
                    for (int q = lane; q < 50; q += 32) dpre[q] = rs[q];
                } else {
                    for (int q = lane; q < 50; q += 32)
                        dpre[q] = ldcg4(&g_stk[r * ENCD + 4 * q]);
                }
            } else {
                for (int q = lane; q < 50; q += 32) dpre[q] = mi4[q];
            }
            // enc: after a shift, fill the fresh ibn slot from REGISTERS
            // (loaded >=1 step ago), then fire next LDG (no consumer now).
            if (lastShift) {
                float4* dbn = (float4*)(sBuf + ibn * 200);
                int row = bp + 1;
                if (row < NSEQ) {
                    dbn[lane] = pf0;
                    if (lane < 18) dbn[lane + 32] = pf1;
                } else {
                    dbn[lane] = mi4[lane];
                    if (lane < 18) dbn[lane + 32] = mi4[lane + 32];
                }
                int nrow = bp + 2;
                if (nrow < NSEQ) {
                    const float4* ep = (const float4*)(g_enc + nrow * ENCD);
                    pf0 = __ldg(&ep[lane]);
                    if (lane < 18) pf1 = __ldg(&ep[lane + 32]);
                }
            }
        }
        pendWp = -1;
        __syncthreads();

        // ==== PHASE B ====
        float m0 = (bp < NSEQ) ? sSc[0] : -1e30f;
        float m1 = (sp >= 2)   ? sSc[1] : -1e30f;
        bool is_shift = (m0 >= m1);   // argmax, first-index tie-break

        if (is_shift) {
            // push FULL b vector: ring + global (CTA-redundant) — no sync
            if (warp == 0 && tid < 25) {
                int slot = sp & (RING_SZ - 1);
                const float4* src = (const float4*)(sBuf + ib * 200);
                float4* rdst = (float4*)(sRing + slot * 200);
                float4 v0 = src[2 * tid], v1 = src[2 * tid + 1];
                rdst[2 * tid] = v0; rdst[2 * tid + 1] = v1;
                stcg4(&g_stk[sp * ENCD + 8 * tid],     v0);
                stcg4(&g_stk[sp * ENCD + 8 * tid + 4], v1);
                if (tid == 0) sTagA[slot] = sp;
            }
            int t = i1; i1 = i0; i0 = ib; ib = ibn; ibn = t;
            sp += 1; bp += 1;
        } else {
            if (warp == 0) {
                if (tid < JC) {
                    int u = tid;
                    int j = jlo + u;
                    float gi = sG[u],          gf1 = sG[JC + u], gf2 = sG[2 * JC + u];
                    float go = sG[3 * JC + u], gu  = sG[4 * JC + u];
                    float c1 = sBuf[i1 * 200 + 100 + j];
                    float c2 = sBuf[i0 * 200 + 100 + j];
                    float c = sigf(gf1) * c1 + sigf(gf2) * c2 + sigf(gi) * tanh_acc(gu);
                    float h = sigf(go) * tanh_acc(c);
                    sBuf[isp * 200 + j]       = h;
                    sBuf[isp * 200 + 100 + j] = c;
                    unsigned int ah = sBufA + (unsigned int)(isp * 200 + j) * 4u;
                    unsigned int ac = sBufA + (unsigned int)(isp * 200 + 100 + j) * 4u;
#pragma unroll
                    for (unsigned int rk = 0; rk < PCLUSTER; rk++) {
                        if (rk != rank) { st_remote_f32(ah, rk, h); st_remote_f32(ac, rk, c); }
                    }
                }
                __syncwarp(0xffffffffu);
                if (tid < PCLUSTER) mbar_arrive_rank(mbarA, (unsigned int)tid);
            }
            mbar_wait_cta(mbarA, (unsigned int)rp);
            rp ^= 1;
            pendWp = sp - 2;           // merged -> ring/g_stk next step
            int n1 = ipre, n0 = isp;
            ipre = i1; isp = i0;
            i1 = n1; i0 = n0;          // merged now at i0
            sp -= 1;
        }
        lastShift = is_shift;
    }

    // final stack[0] = last merged = sBuf[i0] (h | c)
    if (rank == 0 && tid < 200) out[tid] = sBuf[i0 * 200 + tid];
}

// ---------------------------------------------------------------------------
extern "C" void kernel_launch(void* const* d_in, const int* in_sizes, int n_in,
                              void* d_out, int out_size)
{
    const int*   tokens  = (const int*)d_in[0];
    const int*   lengths = (const int*)d_in[1];
    const float* emb     = (const float*)d_in[2];
    const float* Wih0    = (const float*)d_in[3];
    const float* Whh0    = (const float*)d_in[4];
    const float* b0      = (const float*)d_in[5];
    const float* Wih12   = (const float*)d_in[6];
    const float* Whh12   = (const float*)d_in[7];
    const float* b12     = (const float*)d_in[8];
    const float* missing = (const float*)d_in[9];
    const float* Wa      = (const float*)d_in[10];
    const float* ba      = (const float*)d_in[11];
    const float* Wt      = (const float*)d_in[12];
    const float* bt      = (const float*)d_in[13];
    float* out = (float*)d_out;

    float *P, *Ya, *Yb, *enc;
    cudaGetSymbolAddress((void**)&P,  g_P);
    cudaGetSymbolAddress((void**)&Ya, g_Ya);
    cudaGetSymbolAddress((void**)&Yb, g_Yb);
    cudaGetSymbolAddress((void**)&enc, g_enc);

    const int parsSmem = PRS_TOTAL * 4;                    // 100736
    cudaFuncSetAttribute(parser8, cudaFuncAttributeMaxDynamicSharedMemorySize, parsSmem);

    dim3 gg(64, 10), rg(64, 2);

    // layer 0
    proj_gemm<<<gg, 256>>>(emb, tokens, Wih0, b0, P, 300);
    lstm_rec<<<rg, 400>>>(P, Whh0, lengths, Ya, nullptr);
    // layer 1
    proj_gemm<<<gg, 256>>>(Ya, nullptr, Wih12, b12, P, 200);
    lstm_rec<<<rg, 400>>>(P, Whh12, lengths, Yb, nullptr);
    // layer 2 (+ fused meanpool -> enc)
    proj_gemm<<<gg, 256>>>(Yb, nullptr, Wih12 + 160000, b12 + 800, P, 200);
    lstm_rec<<<rg, 400>>>(P, Whh12 + 80000, lengths, nullptr, enc);
    // parse
    parser8<<<PCLUSTER, PR_THREADS, parsSmem>>>(missing, Wa, ba, Wt, bt, out);
}